// round 6
// baseline (speedup 1.0000x reference)
#include <cuda_runtime.h>

// Problem constants
#define NN 32
#define CC 64
#define TTT 256
#define VV 25
#define RR 8
#define OO 64
#define SS 3
#define STREAM_ELEMS (NN*OO*TTT*VV)   // 13,107,200
#define NTV (NN*TTT*VV)               // 204,800
#define AROW 652                      // padded o-row: 25 u * 26 + pad, 16B-aligned stride

typedef unsigned long long u64;

__device__ __forceinline__ u64 pack2(float lo, float hi) {
    u64 r; asm("mov.b64 %0,{%1,%2};" : "=l"(r) : "f"(lo), "f"(hi)); return r;
}
__device__ __forceinline__ void unpack2(u64 p, float& lo, float& hi) {
    asm("mov.b64 {%0,%1},%2;" : "=f"(lo), "=f"(hi) : "l"(p));
}
__device__ __forceinline__ void ffma2(u64& d, u64 a, u64 b) {
    asm("fma.rn.f32x2 %0,%1,%2,%0;" : "+l"(d) : "l"(a), "l"(b));
}

// ---------------- scratch ----------------------------------------------------
__device__ float g_xm[2][NN][CC][VV];
__device__ float g_r[2][SS][NN][RR][VV];
__device__ float g_a[2][SS][NN][OO][AROW];         // padded rows (~32 MB)
__device__ u64   g_wp[2][SS][4][CC][8];            // dup weight pairs per o-tile
__device__ u64   g_bp[2][SS][4][8];                // dup bias pairs
__device__ float g_sum[2][OO];
__device__ float g_sumsq[2][OO];
__device__ float g_mean[2][OO];
__device__ float g_rstd[2][OO];

// ---------------- K1: mean over T (+ zero stats in block 0) ------------------
__global__ void k_mean(const float* __restrict__ x1, const float* __restrict__ x2) {
    int b   = blockIdx.x;
    int tid = threadIdx.x;
    if (b == 0 && tid < 2*OO) {
        ((float*)g_sum)[tid]   = 0.f;
        ((float*)g_sumsq)[tid] = 0.f;
    }
    int s   = b / (NN*CC);
    int rem = b % (NN*CC);
    const float* x = s ? x2 : x1;
    const float* p = x + (size_t)rem * TTT * VV;
    float acc = 0.f;
    #pragma unroll
    for (int k = 0; k < 8; k++) acc += p[tid + k*800];
    __shared__ float part[800];
    part[tid] = acc;
    __syncthreads();
    if (tid < VV) {
        float sum = 0.f;
        #pragma unroll
        for (int tg = 0; tg < 32; tg++) sum += part[tg*VV + tid];
        g_xm[s][rem/CC][rem%CC][tid] = sum * (1.0f/TTT);
    }
}

// ---------------- K2: r = w·xm + b ------------------------------------------
__global__ void k_r(const float* __restrict__ c1w, const float* __restrict__ c1b,
                    const float* __restrict__ c2w, const float* __restrict__ c2b) {
    int i = blockIdx.x / NN, n = blockIdx.x % NN;
    int tid = threadIdx.x;
    if (tid >= 2*RR*VV) return;
    int s  = tid / (RR*VV);
    int rv = tid % (RR*VV);
    int r  = rv / VV, v = rv % VV;
    const float* w  = s ? c2w : c1w;
    const float* bb = s ? c2b : c1b;
    const float* wrow = w + (i*RR + r)*CC;
    const float* xm   = &g_xm[s][n][0][v];
    float acc = bb[i*RR + r];
    #pragma unroll 8
    for (int c = 0; c < CC; c++) acc += wrow[c] * xm[c*VV];
    g_r[s][i][n][r][v] = acc;
}

// ---------------- K2b: pack conv3/conv4 weights + biases as dup pairs --------
__global__ void k_wpack(const float* __restrict__ c3w, const float* __restrict__ c3b,
                        const float* __restrict__ c4w, const float* __restrict__ c4b) {
    int idx = blockIdx.x*512 + threadIdx.x;
    if (idx < 2*SS*4*CC*8) {
        int j  = idx & 7;
        int c  = (idx >> 3) & 63;
        int r  = idx >> 9;            // s*12 + i*4 + ot
        int ot = r & 3;
        int i  = (r >> 2) % SS;
        int s  = r / (SS*4) ;
        const float* w = s ? c4w : c3w;
        int o = ot*16 + 2*j;
        g_wp[s][i][ot][c][j] = pack2(w[(i*OO + o)*CC + c], w[(i*OO + o + 1)*CC + c]);
    }
    if (idx < 2*SS*4*8) {
        int j  = idx & 7;
        int ot = (idx >> 3) & 3;
        int i  = (idx >> 5) % SS;
        int s  = idx / (SS*32);
        const float* b = s ? c4b : c3b;
        int o = ot*16 + 2*j;
        g_bp[s][i][ot][j] = pack2(b[i*OO + o], b[i*OO + o + 1]);
    }
}

// ---------------- K3: rel=tanh(r1-r2); a1,a2 -> padded g_a -------------------
__global__ void k_a(const float* __restrict__ PA, const float* __restrict__ alpha,
                    const float* __restrict__ c5w, const float* __restrict__ c5b,
                    const float* __restrict__ c6w, const float* __restrict__ c6b) {
    int bx = blockIdx.x;                 // o-quarter
    int i  = blockIdx.y / NN, n = blockIdx.y % NN;
    __shared__ float rel[RR][VV*VV];
    __shared__ float r1s[RR][VV], r2s[RR][VV];
    __shared__ u64  wp_s[16*RR];
    int tid = threadIdx.x;
    if (tid < RR*VV) {
        int r = tid/VV, v = tid%VV;
        r1s[r][v] = g_r[0][i][n][r][v];
        r2s[r][v] = g_r[1][i][n][r][v];
    }
    if (tid < 16*RR) {
        int o = tid / RR, r = tid % RR;
        int idx = (i*OO + bx*16 + o)*RR + r;
        wp_s[tid] = pack2(c5w[idx], c6w[idx]);
    }
    __syncthreads();
    {
        int r = 0, uv = tid;             // tid < 256 <= 625
        int u = uv / VV, v = uv - u*VV;
        while (r < RR) {
            rel[r][uv] = tanhf(r1s[r][u] - r2s[r][v]);
            uv += 256;
            if (uv >= VV*VV) { uv -= VV*VV; r++; }
            u = uv / VV; v = uv - u*VV;
        }
    }
    __syncthreads();
    float al = alpha[0];
    {
        int ol = 0, uv = tid;
        while (ol < 16) {
            int o = bx*16 + ol;
            int u = uv / VV, v = uv - u*VV;
            float a1 = c5b[i*OO + o] + PA[i*VV*VV + uv];
            float a2 = c6b[i*OO + o] + al;
            u64 acc = pack2(a1, a2);
            #pragma unroll
            for (int r = 0; r < RR; r++) {
                float rv = rel[r][uv];
                ffma2(acc, wp_s[ol*RR + r], pack2(rv, rv));
            }
            float lo, hi; unpack2(acc, lo, hi);
            g_a[0][i][n][o][u*26 + v] = lo;
            g_a[1][i][n][o][u*26 + v] = hi;
            uv += 256;
            if (uv >= VV*VV) { uv -= VV*VV; ol++; }
        }
    }
}

// ---------------- K4: fused conv1x1 + graph contraction ----------------------
// block = (t-tile 32, o-tile 16, (s,n)); 512 threads, 2 blocks/SM.
// smem: x3s f32[16][832] only (53248 B).
#define SMEM_BYTES (16*832*4)

__global__ void __launch_bounds__(512, 2)
k_main(const float* __restrict__ x1, const float* __restrict__ x2,
       float* __restrict__ out) {
    extern __shared__ __align__(16) float x3s[];   // [16][832]

    int tt0   = blockIdx.x * 32;
    int oty   = blockIdx.y;
    int obase = oty * 16;
    int z     = blockIdx.z;
    int s     = z >> 5;
    int n     = z & 31;
    const float* x = s ? x2 : x1;
    float* yout = out + (size_t)s * STREAM_ELEMS;

    int tid  = threadIdx.x;
    int wid  = tid >> 5;                // phase-2: warp -> o in tile
    int lane = tid & 31;                // phase-2: lane -> t in tile

    float yacc[VV];
    #pragma unroll
    for (int u = 0; u < VV; u++) yacc[u] = 0.f;

    const float* xbase = x + ((size_t)n*CC)*TTT*VV + (size_t)tt0*VV;

    for (int i = 0; i < SS; i++) {
        __syncthreads();   // prev subset's phase-2 reads done before overwrite

        // ---- phase 1: x3[ol][t][v] = sum_c w·x + b   (w via uniform LDG)
        if (tid < 400) {
            const u64* wb = &g_wp[s][i][oty][0][0];
            #pragma unroll
            for (int rep = 0; rep < 2; rep++) {
                int p = tid + rep*400;        // 0..799 in 32x25 tile
                u64 acc[8];
                #pragma unroll
                for (int j = 0; j < 8; j++) acc[j] = __ldg(&g_bp[s][i][oty][j]);
                const float* xp = xbase + p;
                #pragma unroll 4
                for (int c = 0; c < CC; c++) {
                    float xv = __ldg(xp + (size_t)c*TTT*VV);
                    u64 xb = pack2(xv, xv);
                    const ulonglong2* wr = (const ulonglong2*)(wb + c*8);
                    ulonglong2 wA = __ldg(wr + 0), wB = __ldg(wr + 1);
                    ffma2(acc[0], xb, wA.x); ffma2(acc[1], xb, wA.y);
                    ffma2(acc[2], xb, wB.x); ffma2(acc[3], xb, wB.y);
                    wA = __ldg(wr + 2); wB = __ldg(wr + 3);
                    ffma2(acc[4], xb, wA.x); ffma2(acc[5], xb, wA.y);
                    ffma2(acc[6], xb, wB.x); ffma2(acc[7], xb, wB.y);
                }
                int t = p / 25, v = p - t*25;
                int tv = t*26 + v;
                #pragma unroll
                for (int j = 0; j < 8; j++) {
                    float lo, hi; unpack2(acc[j], lo, hi);
                    x3s[(2*j  )*832 + tv] = lo;
                    x3s[(2*j+1)*832 + tv] = hi;
                }
            }
        }
        __syncthreads();

        // ---- phase 2: y[t][u] += sum_v a[o][u][v] * x3[o][t][v]
        {
            const float* ga = &g_a[s][i][n][obase + wid][0];   // padded row
            const u64* xrow = (const u64*)&x3s[wid*832 + lane*26];
            u64 xp2[12];
            #pragma unroll
            for (int j = 0; j < 12; j++) xp2[j] = xrow[j];
            float xlast = x3s[wid*832 + lane*26 + 24];
            #pragma unroll
            for (int u = 0; u < VV; u++) {
                const u64* ar = (const u64*)(ga + u*26);
                u64 accA = 0ull, accB = 0ull;
                #pragma unroll
                for (int j = 0; j < 12; j += 2) {
                    ffma2(accA, __ldg(ar + j),     xp2[j]);
                    ffma2(accB, __ldg(ar + j + 1), xp2[j+1]);
                }
                float a0, a1, b0, b1;
                unpack2(accA, a0, a1); unpack2(accB, b0, b1);
                yacc[u] += (a0 + a1) + (b0 + b1) + __ldg(ga + u*26 + 24) * xlast;
            }
        }
    }

    // ---- channel stats from registers
    {
        int o = obase + wid;
        float ls = 0.f, lq = 0.f;
        #pragma unroll
        for (int u = 0; u < VV; u++) { float yv = yacc[u]; ls += yv; lq += yv*yv; }
        #pragma unroll
        for (int off = 16; off; off >>= 1) {
            ls += __shfl_down_sync(0xffffffffu, ls, off);
            lq += __shfl_down_sync(0xffffffffu, lq, off);
        }
        if (lane == 0) {
            atomicAdd(&g_sum[s][o],   ls);
            atomicAdd(&g_sumsq[s][o], lq);
        }
    }

    // ---- stage y through smem, then coalesced float4 store
    __syncthreads();                       // phase-2 reads of x3s complete
    #pragma unroll
    for (int u = 0; u < VV; u++)
        x3s[wid*832 + lane*25 + u] = yacc[u];
    __syncthreads();
    {
        // 16 rows x 800 floats = 3200 float4
        for (int q = tid; q < 3200; q += 512) {
            int ol = q / 200, k4 = q - ol*200;
            float4 val = *(const float4*)&x3s[ol*832 + k4*4];
            float* dst = yout + (size_t)(n*OO + obase + ol)*TTT*VV + tt0*VV + k4*4;
            *(float4*)dst = val;
        }
    }
}

// ---------------- K5 ---------------------------------------------------------
__global__ void k_stats() {
    int i = threadIdx.x;
    if (i < 2*OO) {
        int s = i / OO, o = i % OO;
        float m = g_sum[s][o] * (1.0f/NTV);
        float v = g_sumsq[s][o] * (1.0f/NTV) - m*m;
        g_mean[s][o] = m;
        g_rstd[s][o] = rsqrtf(v + 1e-5f);
    }
}

// ---------------- K6: BN + residual + ReLU -----------------------------------
__global__ void k_bn(const float* __restrict__ x1, const float* __restrict__ x2,
                     const float* __restrict__ bn1w, const float* __restrict__ bn1b,
                     const float* __restrict__ bn2w, const float* __restrict__ bn2b,
                     float* __restrict__ out) {
    const long total4 = 2L * STREAM_ELEMS / 4;
    long stride = (long)gridDim.x * blockDim.x;
    for (long q = (long)blockIdx.x * blockDim.x + threadIdx.x; q < total4; q += stride) {
        long e   = q * 4;
        int  s   = (int)(e / STREAM_ELEMS);
        long rem = e % STREAM_ELEMS;
        int  o   = (int)((rem / (TTT*VV)) % OO);
        const float* bw = s ? bn2w : bn1w;
        const float* bb = s ? bn2b : bn1b;
        const float* xr = s ? x2   : x1;
        float m  = g_mean[s][o], rs = g_rstd[s][o];
        float sc = rs * bw[o];
        float sh = bb[o] - m * sc;
        float4 yv = ((float4*)out)[q];
        float4 xv = ((const float4*)xr)[rem/4];
        yv.x = fmaxf(fmaf(yv.x, sc, sh) + xv.x, 0.f);
        yv.y = fmaxf(fmaf(yv.y, sc, sh) + xv.y, 0.f);
        yv.z = fmaxf(fmaf(yv.z, sc, sh) + xv.z, 0.f);
        yv.w = fmaxf(fmaf(yv.w, sc, sh) + xv.w, 0.f);
        ((float4*)out)[q] = yv;
    }
}

// ---------------- launcher ---------------------------------------------------
extern "C" void kernel_launch(void* const* d_in, const int* in_sizes, int n_in,
                              void* d_out, int out_size) {
    const float* x1    = (const float*)d_in[0];
    const float* x2    = (const float*)d_in[1];
    const float* PA    = (const float*)d_in[2];
    const float* alpha = (const float*)d_in[3];
    const float* c1w   = (const float*)d_in[4];
    const float* c1b   = (const float*)d_in[5];
    const float* c2w   = (const float*)d_in[6];
    const float* c2b   = (const float*)d_in[7];
    const float* c3w   = (const float*)d_in[8];
    const float* c3b   = (const float*)d_in[9];
    const float* c4w   = (const float*)d_in[10];
    const float* c4b   = (const float*)d_in[11];
    const float* c5w   = (const float*)d_in[12];
    const float* c5b   = (const float*)d_in[13];
    const float* c6w   = (const float*)d_in[14];
    const float* c6b   = (const float*)d_in[15];
    const float* bn1w  = (const float*)d_in[16];
    const float* bn1b  = (const float*)d_in[17];
    const float* bn2w  = (const float*)d_in[18];
    const float* bn2b  = (const float*)d_in[19];
    float* out = (float*)d_out;

    cudaFuncSetAttribute(k_main, cudaFuncAttributeMaxDynamicSharedMemorySize, SMEM_BYTES);

    k_mean<<<2*NN*CC, 800>>>(x1, x2);
    k_wpack<<<24, 512>>>(c3w, c3b, c4w, c4b);
    k_r<<<SS*NN, 512>>>(c1w, c1b, c2w, c2b);
    k_a<<<dim3(4, SS*NN), 256>>>(PA, alpha, c5w, c5b, c6w, c6b);
    k_main<<<dim3(TTT/32, 4, 2*NN), 512, SMEM_BYTES>>>(x1, x2, out);
    k_stats<<<1, 128>>>();
    k_bn<<<8192, 256>>>(x1, x2, bn1w, bn1b, bn2w, bn2b, out);
}

// round 7
// speedup vs baseline: 2.2266x; 2.2266x over previous
#include <cuda_runtime.h>

// Problem constants
#define NN 32
#define CC 64
#define TTT 256
#define VV 25
#define RR 8
#define OO 64
#define SS 3
#define STREAM_ELEMS (NN*OO*TTT*VV)   // 13,107,200
#define NTV (NN*TTT*VV)               // 204,800
#define AROW 652                      // padded a-row per o: 25u*26 + pad (16B-mult)

typedef unsigned long long u64;

__device__ __forceinline__ u64 pack2(float lo, float hi) {
    u64 r; asm("mov.b64 %0,{%1,%2};" : "=l"(r) : "f"(lo), "f"(hi)); return r;
}
__device__ __forceinline__ void unpack2(u64 p, float& lo, float& hi) {
    asm("mov.b64 {%0,%1},%2;" : "=f"(lo), "=f"(hi) : "l"(p));
}
__device__ __forceinline__ void ffma2(u64& d, u64 a, u64 b) {
    asm("fma.rn.f32x2 %0,%1,%2,%0;" : "+l"(d) : "l"(a), "l"(b));
}

// ---------------- scratch ----------------------------------------------------
__device__ float g_xm[2][NN][CC][VV];
__device__ float g_r[2][SS][NN][RR][VV];
__device__ float g_a[2][SS][NN][OO][AROW];         // padded rows (~32 MB)
__device__ float g_sum[2][OO];
__device__ float g_sumsq[2][OO];
__device__ float g_mean[2][OO];
__device__ float g_rstd[2][OO];

// ---------------- K1: mean over T (+ zero stats in block 0) ------------------
__global__ void k_mean(const float* __restrict__ x1, const float* __restrict__ x2) {
    int b   = blockIdx.x;
    int tid = threadIdx.x;
    if (b == 0 && tid < 2*OO) {
        ((float*)g_sum)[tid]   = 0.f;
        ((float*)g_sumsq)[tid] = 0.f;
    }
    int s   = b / (NN*CC);
    int rem = b % (NN*CC);
    const float* x = s ? x2 : x1;
    const float* p = x + (size_t)rem * TTT * VV;
    float acc = 0.f;
    #pragma unroll
    for (int k = 0; k < 8; k++) acc += p[tid + k*800];
    __shared__ float part[800];
    part[tid] = acc;
    __syncthreads();
    if (tid < VV) {
        float sum = 0.f;
        #pragma unroll
        for (int tg = 0; tg < 32; tg++) sum += part[tg*VV + tid];
        g_xm[s][rem/CC][rem%CC][tid] = sum * (1.0f/TTT);
    }
}

// ---------------- K2: r = w·xm + b ------------------------------------------
__global__ void k_r(const float* __restrict__ c1w, const float* __restrict__ c1b,
                    const float* __restrict__ c2w, const float* __restrict__ c2b) {
    int i = blockIdx.x / NN, n = blockIdx.x % NN;
    int tid = threadIdx.x;
    if (tid >= 2*RR*VV) return;
    int s  = tid / (RR*VV);
    int rv = tid % (RR*VV);
    int r  = rv / VV, v = rv % VV;
    const float* w  = s ? c2w : c1w;
    const float* bb = s ? c2b : c1b;
    const float* wrow = w + (i*RR + r)*CC;
    const float* xm   = &g_xm[s][n][0][v];
    float acc = bb[i*RR + r];
    #pragma unroll 8
    for (int c = 0; c < CC; c++) acc += wrow[c] * xm[c*VV];
    g_r[s][i][n][r][v] = acc;
}

// ---------------- K3: rel=tanh(r1-r2); a1,a2 -> padded g_a -------------------
__global__ void k_a(const float* __restrict__ PA, const float* __restrict__ alpha,
                    const float* __restrict__ c5w, const float* __restrict__ c5b,
                    const float* __restrict__ c6w, const float* __restrict__ c6b) {
    int bx = blockIdx.x;                 // o-quarter
    int i  = blockIdx.y / NN, n = blockIdx.y % NN;
    __shared__ float rel[RR][VV*VV];
    __shared__ float r1s[RR][VV], r2s[RR][VV];
    __shared__ u64  wp_s[16*RR];
    int tid = threadIdx.x;
    if (tid < RR*VV) {
        int r = tid/VV, v = tid%VV;
        r1s[r][v] = g_r[0][i][n][r][v];
        r2s[r][v] = g_r[1][i][n][r][v];
    }
    if (tid < 16*RR) {
        int o = tid / RR, r = tid % RR;
        int idx = (i*OO + bx*16 + o)*RR + r;
        wp_s[tid] = pack2(c5w[idx], c6w[idx]);
    }
    __syncthreads();
    {
        int r = 0, uv = tid;
        int u = uv / VV, v = uv - u*VV;
        while (r < RR) {
            rel[r][uv] = tanhf(r1s[r][u] - r2s[r][v]);
            uv += 256;
            if (uv >= VV*VV) { uv -= VV*VV; r++; }
            u = uv / VV; v = uv - u*VV;
        }
    }
    __syncthreads();
    float al = alpha[0];
    {
        int ol = 0, uv = tid;
        while (ol < 16) {
            int o = bx*16 + ol;
            int u = uv / VV, v = uv - u*VV;
            float a1 = c5b[i*OO + o] + PA[i*VV*VV + uv];
            float a2 = c6b[i*OO + o] + al;
            u64 acc = pack2(a1, a2);
            #pragma unroll
            for (int r = 0; r < RR; r++) {
                float rv = rel[r][uv];
                ffma2(acc, wp_s[ol*RR + r], pack2(rv, rv));
            }
            float lo, hi; unpack2(acc, lo, hi);
            g_a[0][i][n][o][u*26 + v] = lo;
            g_a[1][i][n][o][u*26 + v] = hi;
            uv += 256;
            if (uv >= VV*VV) { uv -= VV*VV; ol++; }
        }
    }
}

// ---------------- K4: fused conv1x1 + graph contraction ----------------------
// block = (t-tile 32, o-tile 8, (s,n)); 256 threads, 3 blocks/SM.
// dyn smem:
//   [0)      wsd : u64[64][4]    (w dup pairs)          2048
//   [2048)   bpr : u64[4]                                 32
//   [2080->2112 pad to 16B]
//   [2112)   x3s : f32[8][832]   (conv tile, row 26)   26624
//   [28736)  as_ : f32[8][652]   (a rows, padded)      20864
#define SM_WSD  0
#define SM_BPR  2048
#define SM_X3S  2112
#define SM_AS   28736
#define SMEM_BYTES (28736 + 20864)   // 49600

__global__ void __launch_bounds__(256, 3)
k_main(const float* __restrict__ x1, const float* __restrict__ x2,
       const float* __restrict__ c3w, const float* __restrict__ c3b,
       const float* __restrict__ c4w, const float* __restrict__ c4b,
       float* __restrict__ out) {
    extern __shared__ __align__(16) char smraw[];
    u64*   wsd = (u64*)(smraw + SM_WSD);
    u64*   bpr = (u64*)(smraw + SM_BPR);
    float* x3s = (float*)(smraw + SM_X3S);
    float* as_ = (float*)(smraw + SM_AS);

    int tt0   = blockIdx.x * 32;
    int obase = blockIdx.y * 8;
    int z     = blockIdx.z;
    int s     = z >> 5;
    int n     = z & 31;
    const float* x  = s ? x2  : x1;
    const float* cw = s ? c4w : c3w;
    const float* cb = s ? c4b : c3b;
    float* yout = out + (size_t)s * STREAM_ELEMS;

    int tid  = threadIdx.x;
    int wid  = tid >> 5;                // phase-2: warp -> o in tile (0..7)
    int lane = tid & 31;                // phase-2: lane -> t in tile

    float yacc[VV];
    #pragma unroll
    for (int u = 0; u < VV; u++) yacc[u] = 0.f;

    const float* xbase = x + ((size_t)n*CC)*TTT*VV + (size_t)tt0*VV;

    for (int i = 0; i < SS; i++) {
        __syncthreads();   // prev subset's phase-2 reads done before restage

        // ---- stage: w dup pairs (256 = 1/thread), bias, a-slice (float4 copy)
        {
            int c = tid >> 2, j = tid & 3;
            int ob = (i*OO + obase + 2*j)*CC + c;
            wsd[tid] = pack2(cw[ob], cw[ob + CC]);
        }
        if (tid < 4)
            bpr[tid] = pack2(cb[i*OO + obase + 2*tid], cb[i*OO + obase + 2*tid + 1]);
        {
            const float4* asrc = (const float4*)&g_a[s][i][n][obase][0]; // 8*652 floats
            float4* adst = (float4*)as_;
            #pragma unroll
            for (int q = tid; q < 8*AROW/4; q += 256) adst[q] = asrc[q];
        }
        __syncthreads();

        // ---- phase 1: x3[ol][t][v] = sum_c w·x + b
        // 200 threads * float4 positions; 4 o-pairs (8 o); 3 B/ffma2.
        if (tid < 200) {
            u64 acc[4][4];
            #pragma unroll
            for (int e = 0; e < 4; e++)
                #pragma unroll
                for (int j = 0; j < 4; j++) acc[e][j] = bpr[j];

            #pragma unroll 4
            for (int c = 0; c < CC; c++) {
                float4 xq = *(const float4*)(xbase + (size_t)c*TTT*VV + tid*4);
                const ulonglong2* wr = (const ulonglong2*)&wsd[c*4];
                ulonglong2 wA = wr[0], wB = wr[1];
                u64 xb0 = pack2(xq.x, xq.x);
                u64 xb1 = pack2(xq.y, xq.y);
                u64 xb2 = pack2(xq.z, xq.z);
                u64 xb3 = pack2(xq.w, xq.w);
                ffma2(acc[0][0], xb0, wA.x); ffma2(acc[0][1], xb0, wA.y);
                ffma2(acc[0][2], xb0, wB.x); ffma2(acc[0][3], xb0, wB.y);
                ffma2(acc[1][0], xb1, wA.x); ffma2(acc[1][1], xb1, wA.y);
                ffma2(acc[1][2], xb1, wB.x); ffma2(acc[1][3], xb1, wB.y);
                ffma2(acc[2][0], xb2, wA.x); ffma2(acc[2][1], xb2, wA.y);
                ffma2(acc[2][2], xb2, wB.x); ffma2(acc[2][3], xb2, wB.y);
                ffma2(acc[3][0], xb3, wA.x); ffma2(acc[3][1], xb3, wA.y);
                ffma2(acc[3][2], xb3, wB.x); ffma2(acc[3][3], xb3, wB.y);
            }
            #pragma unroll
            for (int e = 0; e < 4; e++) {
                int p = tid*4 + e;            // < 800
                int t = p / 25, v = p - t*25;
                int tv = t*26 + v;
                #pragma unroll
                for (int j = 0; j < 4; j++) {
                    float lo, hi; unpack2(acc[e][j], lo, hi);
                    x3s[(2*j  )*832 + tv] = lo;
                    x3s[(2*j+1)*832 + tv] = hi;
                }
            }
        }
        __syncthreads();

        // ---- phase 2: y[t][u] += sum_v a[wid][u][v] * x3[wid][t][v]
        {
            const u64* xrow = (const u64*)&x3s[wid*832 + lane*26];
            u64 xp2[12];
            #pragma unroll
            for (int j = 0; j < 12; j++) xp2[j] = xrow[j];
            float xlast = x3s[wid*832 + lane*26 + 24];
            const float* ga = &as_[wid*AROW];
            #pragma unroll
            for (int u = 0; u < VV; u++) {
                const u64* ar = (const u64*)(ga + u*26);
                u64 accA = 0ull, accB = 0ull;
                #pragma unroll
                for (int j = 0; j < 12; j += 2) {
                    ffma2(accA, ar[j],   xp2[j]);
                    ffma2(accB, ar[j+1], xp2[j+1]);
                }
                float a0, a1, b0, b1;
                unpack2(accA, a0, a1); unpack2(accB, b0, b1);
                yacc[u] += (a0 + a1) + (b0 + b1) + ga[u*26 + 24] * xlast;
            }
        }
    }

    // ---- channel stats from registers
    {
        int o = obase + wid;
        float ls = 0.f, lq = 0.f;
        #pragma unroll
        for (int u = 0; u < VV; u++) { float yv = yacc[u]; ls += yv; lq += yv*yv; }
        #pragma unroll
        for (int off = 16; off; off >>= 1) {
            ls += __shfl_down_sync(0xffffffffu, ls, off);
            lq += __shfl_down_sync(0xffffffffu, lq, off);
        }
        if (lane == 0) {
            atomicAdd(&g_sum[s][o],   ls);
            atomicAdd(&g_sumsq[s][o], lq);
        }
    }

    // ---- stage y through smem, then coalesced float4 store
    __syncthreads();                       // all phase-2 x3s reads complete
    #pragma unroll
    for (int u = 0; u < VV; u++)
        x3s[wid*832 + lane*25 + u] = yacc[u];
    __syncthreads();
    {
        // 8 rows x 800 floats = 1600 float4
        #pragma unroll
        for (int q = tid; q < 1600; q += 256) {
            int ol = q / 200, k4 = q - ol*200;
            float4 val = *(const float4*)&x3s[ol*832 + k4*4];
            float* dst = yout + (size_t)(n*OO + obase + ol)*TTT*VV + tt0*VV + k4*4;
            *(float4*)dst = val;
        }
    }
}

// ---------------- K5 ---------------------------------------------------------
__global__ void k_stats() {
    int i = threadIdx.x;
    if (i < 2*OO) {
        int s = i / OO, o = i % OO;
        float m = g_sum[s][o] * (1.0f/NTV);
        float v = g_sumsq[s][o] * (1.0f/NTV) - m*m;
        g_mean[s][o] = m;
        g_rstd[s][o] = rsqrtf(v + 1e-5f);
    }
}

// ---------------- K6: BN + residual + ReLU -----------------------------------
__global__ void k_bn(const float* __restrict__ x1, const float* __restrict__ x2,
                     const float* __restrict__ bn1w, const float* __restrict__ bn1b,
                     const float* __restrict__ bn2w, const float* __restrict__ bn2b,
                     float* __restrict__ out) {
    const long total4 = 2L * STREAM_ELEMS / 4;
    long stride = (long)gridDim.x * blockDim.x;
    for (long q = (long)blockIdx.x * blockDim.x + threadIdx.x; q < total4; q += stride) {
        long e   = q * 4;
        int  s   = (int)(e / STREAM_ELEMS);
        long rem = e % STREAM_ELEMS;
        int  o   = (int)((rem / (TTT*VV)) % OO);
        const float* bw = s ? bn2w : bn1w;
        const float* bb = s ? bn2b : bn1b;
        const float* xr = s ? x2   : x1;
        float m  = g_mean[s][o], rs = g_rstd[s][o];
        float sc = rs * bw[o];
        float sh = bb[o] - m * sc;
        float4 yv = ((float4*)out)[q];
        float4 xv = ((const float4*)xr)[rem/4];
        yv.x = fmaxf(fmaf(yv.x, sc, sh) + xv.x, 0.f);
        yv.y = fmaxf(fmaf(yv.y, sc, sh) + xv.y, 0.f);
        yv.z = fmaxf(fmaf(yv.z, sc, sh) + xv.z, 0.f);
        yv.w = fmaxf(fmaf(yv.w, sc, sh) + xv.w, 0.f);
        ((float4*)out)[q] = yv;
    }
}

// ---------------- launcher ---------------------------------------------------
extern "C" void kernel_launch(void* const* d_in, const int* in_sizes, int n_in,
                              void* d_out, int out_size) {
    const float* x1    = (const float*)d_in[0];
    const float* x2    = (const float*)d_in[1];
    const float* PA    = (const float*)d_in[2];
    const float* alpha = (const float*)d_in[3];
    const float* c1w   = (const float*)d_in[4];
    const float* c1b   = (const float*)d_in[5];
    const float* c2w   = (const float*)d_in[6];
    const float* c2b   = (const float*)d_in[7];
    const float* c3w   = (const float*)d_in[8];
    const float* c3b   = (const float*)d_in[9];
    const float* c4w   = (const float*)d_in[10];
    const float* c4b   = (const float*)d_in[11];
    const float* c5w   = (const float*)d_in[12];
    const float* c5b   = (const float*)d_in[13];
    const float* c6w   = (const float*)d_in[14];
    const float* c6b   = (const float*)d_in[15];
    const float* bn1w  = (const float*)d_in[16];
    const float* bn1b  = (const float*)d_in[17];
    const float* bn2w  = (const float*)d_in[18];
    const float* bn2b  = (const float*)d_in[19];
    float* out = (float*)d_out;

    cudaFuncSetAttribute(k_main, cudaFuncAttributeMaxDynamicSharedMemorySize, SMEM_BYTES);

    k_mean<<<2*NN*CC, 800>>>(x1, x2);
    k_r<<<SS*NN, 512>>>(c1w, c1b, c2w, c2b);
    k_a<<<dim3(4, SS*NN), 256>>>(PA, alpha, c5w, c5b, c6w, c6b);
    k_main<<<dim3(TTT/32, OO/8, 2*NN), 256, SMEM_BYTES>>>(x1, x2, c3w, c3b, c4w, c4b, out);
    k_stats<<<1, 128>>>();
    k_bn<<<8192, 256>>>(x1, x2, bn1w, bn1b, bn2w, bn2b, out);
}

// round 8
// speedup vs baseline: 2.4677x; 1.1083x over previous
#include <cuda_runtime.h>

// Problem constants
#define NN 32
#define CC 64
#define TTT 256
#define VV 25
#define RR 8
#define OO 64
#define SS 3
#define STREAM_ELEMS (NN*OO*TTT*VV)   // 13,107,200
#define NTV (NN*TTT*VV)               // 204,800
#define AROW 652                      // padded a-row per o: 25u*26 + pad (16B-mult)

typedef unsigned long long u64;

__device__ __forceinline__ u64 pack2(float lo, float hi) {
    u64 r; asm("mov.b64 %0,{%1,%2};" : "=l"(r) : "f"(lo), "f"(hi)); return r;
}
__device__ __forceinline__ void unpack2(u64 p, float& lo, float& hi) {
    asm("mov.b64 {%0,%1},%2;" : "=f"(lo), "=f"(hi) : "l"(p));
}
__device__ __forceinline__ void ffma2(u64& d, u64 a, u64 b) {
    asm("fma.rn.f32x2 %0,%1,%2,%0;" : "+l"(d) : "l"(a), "l"(b));
}

// ---------------- scratch ----------------------------------------------------
__device__ float g_xm[2][NN][CC][VV];
__device__ float g_r[2][SS][NN][RR][VV];
__device__ float g_a[2][SS][NN][OO][AROW];         // padded rows (~32 MB)
__device__ float g_sum[2][OO];
__device__ float g_sumsq[2][OO];
__device__ float g_mean[2][OO];
__device__ float g_rstd[2][OO];

// ---------------- K1: mean over T (+ zero stats in block 0) ------------------
__global__ void k_mean(const float* __restrict__ x1, const float* __restrict__ x2) {
    int b   = blockIdx.x;
    int tid = threadIdx.x;
    if (b == 0 && tid < 2*OO) {
        ((float*)g_sum)[tid]   = 0.f;
        ((float*)g_sumsq)[tid] = 0.f;
    }
    int s   = b / (NN*CC);
    int rem = b % (NN*CC);
    const float* x = s ? x2 : x1;
    const float* p = x + (size_t)rem * TTT * VV;
    float acc = 0.f;
    #pragma unroll
    for (int k = 0; k < 8; k++) acc += p[tid + k*800];
    __shared__ float part[800];
    part[tid] = acc;
    __syncthreads();
    if (tid < VV) {
        float sum = 0.f;
        #pragma unroll
        for (int tg = 0; tg < 32; tg++) sum += part[tg*VV + tid];
        g_xm[s][rem/CC][rem%CC][tid] = sum * (1.0f/TTT);
    }
}

// ---------------- K2: r = w·xm + b ------------------------------------------
__global__ void k_r(const float* __restrict__ c1w, const float* __restrict__ c1b,
                    const float* __restrict__ c2w, const float* __restrict__ c2b) {
    int i = blockIdx.x / NN, n = blockIdx.x % NN;
    int tid = threadIdx.x;
    if (tid >= 2*RR*VV) return;
    int s  = tid / (RR*VV);
    int rv = tid % (RR*VV);
    int r  = rv / VV, v = rv % VV;
    const float* w  = s ? c2w : c1w;
    const float* bb = s ? c2b : c1b;
    const float* wrow = w + (i*RR + r)*CC;
    const float* xm   = &g_xm[s][n][0][v];
    float acc = bb[i*RR + r];
    #pragma unroll 8
    for (int c = 0; c < CC; c++) acc += wrow[c] * xm[c*VV];
    g_r[s][i][n][r][v] = acc;
}

// ---------------- K3: rel=tanh(r1-r2); a1,a2 -> padded g_a -------------------
__global__ void k_a(const float* __restrict__ PA, const float* __restrict__ alpha,
                    const float* __restrict__ c5w, const float* __restrict__ c5b,
                    const float* __restrict__ c6w, const float* __restrict__ c6b) {
    int bx = blockIdx.x;                 // o-quarter
    int i  = blockIdx.y / NN, n = blockIdx.y % NN;
    __shared__ float rel[RR][VV*VV];
    __shared__ float r1s[RR][VV], r2s[RR][VV];
    __shared__ u64  wp_s[16*RR];
    int tid = threadIdx.x;
    if (tid < RR*VV) {
        int r = tid/VV, v = tid%VV;
        r1s[r][v] = g_r[0][i][n][r][v];
        r2s[r][v] = g_r[1][i][n][r][v];
    }
    if (tid < 16*RR) {
        int o = tid / RR, r = tid % RR;
        int idx = (i*OO + bx*16 + o)*RR + r;
        wp_s[tid] = pack2(c5w[idx], c6w[idx]);
    }
    __syncthreads();
    {
        int r = 0, uv = tid;
        int u = uv / VV, v = uv - u*VV;
        while (r < RR) {
            rel[r][uv] = tanhf(r1s[r][u] - r2s[r][v]);
            uv += 256;
            if (uv >= VV*VV) { uv -= VV*VV; r++; }
            u = uv / VV; v = uv - u*VV;
        }
    }
    __syncthreads();
    float al = alpha[0];
    {
        int ol = 0, uv = tid;
        while (ol < 16) {
            int o = bx*16 + ol;
            int u = uv / VV, v = uv - u*VV;
            float a1 = c5b[i*OO + o] + PA[i*VV*VV + uv];
            float a2 = c6b[i*OO + o] + al;
            u64 acc = pack2(a1, a2);
            #pragma unroll
            for (int r = 0; r < RR; r++) {
                float rv = rel[r][uv];
                ffma2(acc, wp_s[ol*RR + r], pack2(rv, rv));
            }
            float lo, hi; unpack2(acc, lo, hi);
            g_a[0][i][n][o][u*26 + v] = lo;
            g_a[1][i][n][o][u*26 + v] = hi;
            uv += 256;
            if (uv >= VV*VV) { uv -= VV*VV; ol++; }
        }
    }
}

// ---------------- K4: fused conv1x1 + graph contraction ----------------------
// block = (t-tile 32, o-tile 8, (s,n)); 256 threads, 4 blocks/SM.
// dyn smem:
//   [0)      wsd : u64[64][4]    (w dup pairs)          2048
//   [2048)   bpr : u64[4]                                 32
//   [2080->2112 pad to 16B]
//   [2112)   x3s : f32[8][832]   (conv tile, row 26)   26624
//   [28736)  as_ : f32[8][652]   (a rows, padded)      20864
#define SM_WSD  0
#define SM_BPR  2048
#define SM_X3S  2112
#define SM_AS   28736
#define SMEM_BYTES (28736 + 20864)   // 49600

__global__ void __launch_bounds__(256, 4)
k_main(const float* __restrict__ x1, const float* __restrict__ x2,
       const float* __restrict__ c3w, const float* __restrict__ c3b,
       const float* __restrict__ c4w, const float* __restrict__ c4b,
       float* __restrict__ out) {
    extern __shared__ __align__(16) char smraw[];
    u64*   wsd = (u64*)(smraw + SM_WSD);
    u64*   bpr = (u64*)(smraw + SM_BPR);
    float* x3s = (float*)(smraw + SM_X3S);
    float* as_ = (float*)(smraw + SM_AS);

    int tt0   = blockIdx.x * 32;
    int obase = blockIdx.y * 8;
    int z     = blockIdx.z;
    int s     = z >> 5;
    int n     = z & 31;
    const float* x  = s ? x2  : x1;
    const float* cw = s ? c4w : c3w;
    const float* cb = s ? c4b : c3b;
    float* yout = out + (size_t)s * STREAM_ELEMS;

    int tid  = threadIdx.x;
    int wid  = tid >> 5;                // phase-2: warp -> o in tile (0..7)
    int lane = tid & 31;                // phase-2: lane -> t in tile

    float yacc[VV];
    #pragma unroll
    for (int u = 0; u < VV; u++) yacc[u] = 0.f;

    const float* xbase = x + ((size_t)n*CC)*TTT*VV + (size_t)tt0*VV;

    for (int i = 0; i < SS; i++) {
        __syncthreads();   // prev subset's phase-2 reads done before restage

        // ---- stage: w dup pairs (256 = 1/thread), bias, a-slice (float4 copy)
        {
            int c = tid >> 2, j = tid & 3;
            int ob = (i*OO + obase + 2*j)*CC + c;
            wsd[tid] = pack2(cw[ob], cw[ob + CC]);
        }
        if (tid < 4)
            bpr[tid] = pack2(cb[i*OO + obase + 2*tid], cb[i*OO + obase + 2*tid + 1]);
        {
            const float4* asrc = (const float4*)&g_a[s][i][n][obase][0]; // 8*652 floats
            float4* adst = (float4*)as_;
            #pragma unroll
            for (int q = tid; q < 8*AROW/4; q += 256) adst[q] = asrc[q];
        }
        __syncthreads();

        // ---- phase 1: x3[ol][t][v] = sum_c w·x + b
        // Two sequential position-passes (float2 each) -> acc regs halved
        // vs float4 single-pass; enables 4 blocks/SM.
        if (tid < 200) {
            #pragma unroll
            for (int pass = 0; pass < 2; pass++) {
                u64 acc[2][4];
                #pragma unroll
                for (int e = 0; e < 2; e++)
                    #pragma unroll
                    for (int j = 0; j < 4; j++) acc[e][j] = bpr[j];

                const float* xp = xbase + pass*400 + tid*2;
                #pragma unroll 8
                for (int c = 0; c < CC; c++) {
                    float2 xq = *(const float2*)(xp + (size_t)c*TTT*VV);
                    const ulonglong2* wr = (const ulonglong2*)&wsd[c*4];
                    ulonglong2 wA = wr[0], wB = wr[1];
                    u64 xb0 = pack2(xq.x, xq.x);
                    u64 xb1 = pack2(xq.y, xq.y);
                    ffma2(acc[0][0], xb0, wA.x); ffma2(acc[0][1], xb0, wA.y);
                    ffma2(acc[0][2], xb0, wB.x); ffma2(acc[0][3], xb0, wB.y);
                    ffma2(acc[1][0], xb1, wA.x); ffma2(acc[1][1], xb1, wA.y);
                    ffma2(acc[1][2], xb1, wB.x); ffma2(acc[1][3], xb1, wB.y);
                }
                #pragma unroll
                for (int e = 0; e < 2; e++) {
                    int p = pass*400 + tid*2 + e;   // < 800
                    int t = p / 25, v = p - t*25;
                    int tv = t*26 + v;
                    #pragma unroll
                    for (int j = 0; j < 4; j++) {
                        float lo, hi; unpack2(acc[e][j], lo, hi);
                        x3s[(2*j  )*832 + tv] = lo;
                        x3s[(2*j+1)*832 + tv] = hi;
                    }
                }
            }
        }
        __syncthreads();

        // ---- phase 2: y[t][u] += sum_v a[wid][u][v] * x3[wid][t][v]
        {
            const u64* xrow = (const u64*)&x3s[wid*832 + lane*26];
            u64 xp2[12];
            #pragma unroll
            for (int j = 0; j < 12; j++) xp2[j] = xrow[j];
            float xlast = x3s[wid*832 + lane*26 + 24];
            const float* ga = &as_[wid*AROW];
            #pragma unroll
            for (int u = 0; u < VV; u++) {
                const u64* ar = (const u64*)(ga + u*26);
                u64 accA = 0ull, accB = 0ull;
                #pragma unroll
                for (int j = 0; j < 12; j += 2) {
                    ffma2(accA, ar[j],   xp2[j]);
                    ffma2(accB, ar[j+1], xp2[j+1]);
                }
                float a0, a1, b0, b1;
                unpack2(accA, a0, a1); unpack2(accB, b0, b1);
                yacc[u] += (a0 + a1) + (b0 + b1) + ga[u*26 + 24] * xlast;
            }
        }
    }

    // ---- channel stats from registers
    {
        int o = obase + wid;
        float ls = 0.f, lq = 0.f;
        #pragma unroll
        for (int u = 0; u < VV; u++) { float yv = yacc[u]; ls += yv; lq += yv*yv; }
        #pragma unroll
        for (int off = 16; off; off >>= 1) {
            ls += __shfl_down_sync(0xffffffffu, ls, off);
            lq += __shfl_down_sync(0xffffffffu, lq, off);
        }
        if (lane == 0) {
            atomicAdd(&g_sum[s][o],   ls);
            atomicAdd(&g_sumsq[s][o], lq);
        }
    }

    // ---- stage y through smem, then coalesced float4 store
    __syncthreads();                       // all phase-2 x3s reads complete
    #pragma unroll
    for (int u = 0; u < VV; u++)
        x3s[wid*832 + lane*25 + u] = yacc[u];
    __syncthreads();
    {
        // 8 rows x 800 floats = 1600 float4
        #pragma unroll
        for (int q = tid; q < 1600; q += 256) {
            int ol = q / 200, k4 = q - ol*200;
            float4 val = *(const float4*)&x3s[ol*832 + k4*4];
            float* dst = yout + (size_t)(n*OO + obase + ol)*TTT*VV + tt0*VV + k4*4;
            *(float4*)dst = val;
        }
    }
}

// ---------------- K5 ---------------------------------------------------------
__global__ void k_stats() {
    int i = threadIdx.x;
    if (i < 2*OO) {
        int s = i / OO, o = i % OO;
        float m = g_sum[s][o] * (1.0f/NTV);
        float v = g_sumsq[s][o] * (1.0f/NTV) - m*m;
        g_mean[s][o] = m;
        g_rstd[s][o] = rsqrtf(v + 1e-5f);
    }
}

// ---------------- K6: BN + residual + ReLU -----------------------------------
__global__ void k_bn(const float* __restrict__ x1, const float* __restrict__ x2,
                     const float* __restrict__ bn1w, const float* __restrict__ bn1b,
                     const float* __restrict__ bn2w, const float* __restrict__ bn2b,
                     float* __restrict__ out) {
    const long total4 = 2L * STREAM_ELEMS / 4;
    long stride = (long)gridDim.x * blockDim.x;
    for (long q = (long)blockIdx.x * blockDim.x + threadIdx.x; q < total4; q += stride) {
        long e   = q * 4;
        int  s   = (int)(e / STREAM_ELEMS);
        long rem = e % STREAM_ELEMS;
        int  o   = (int)((rem / (TTT*VV)) % OO);
        const float* bw = s ? bn2w : bn1w;
        const float* bb = s ? bn2b : bn1b;
        const float* xr = s ? x2   : x1;
        float m  = g_mean[s][o], rs = g_rstd[s][o];
        float sc = rs * bw[o];
        float sh = bb[o] - m * sc;
        float4 yv = ((float4*)out)[q];
        float4 xv = ((const float4*)xr)[rem/4];
        yv.x = fmaxf(fmaf(yv.x, sc, sh) + xv.x, 0.f);
        yv.y = fmaxf(fmaf(yv.y, sc, sh) + xv.y, 0.f);
        yv.z = fmaxf(fmaf(yv.z, sc, sh) + xv.z, 0.f);
        yv.w = fmaxf(fmaf(yv.w, sc, sh) + xv.w, 0.f);
        ((float4*)out)[q] = yv;
    }
}

// ---------------- launcher ---------------------------------------------------
extern "C" void kernel_launch(void* const* d_in, const int* in_sizes, int n_in,
                              void* d_out, int out_size) {
    const float* x1    = (const float*)d_in[0];
    const float* x2    = (const float*)d_in[1];
    const float* PA    = (const float*)d_in[2];
    const float* alpha = (const float*)d_in[3];
    const float* c1w   = (const float*)d_in[4];
    const float* c1b   = (const float*)d_in[5];
    const float* c2w   = (const float*)d_in[6];
    const float* c2b   = (const float*)d_in[7];
    const float* c3w   = (const float*)d_in[8];
    const float* c3b   = (const float*)d_in[9];
    const float* c4w   = (const float*)d_in[10];
    const float* c4b   = (const float*)d_in[11];
    const float* c5w   = (const float*)d_in[12];
    const float* c5b   = (const float*)d_in[13];
    const float* c6w   = (const float*)d_in[14];
    const float* c6b   = (const float*)d_in[15];
    const float* bn1w  = (const float*)d_in[16];
    const float* bn1b  = (const float*)d_in[17];
    const float* bn2w  = (const float*)d_in[18];
    const float* bn2b  = (const float*)d_in[19];
    float* out = (float*)d_out;

    cudaFuncSetAttribute(k_main, cudaFuncAttributeMaxDynamicSharedMemorySize, SMEM_BYTES);

    k_mean<<<2*NN*CC, 800>>>(x1, x2);
    k_r<<<SS*NN, 512>>>(c1w, c1b, c2w, c2b);
    k_a<<<dim3(4, SS*NN), 256>>>(PA, alpha, c5w, c5b, c6w, c6b);
    k_main<<<dim3(TTT/32, OO/8, 2*NN), 256, SMEM_BYTES>>>(x1, x2, c3w, c3b, c4w, c4b, out);
    k_stats<<<1, 128>>>();
    k_bn<<<8192, 256>>>(x1, x2, bn1w, bn1b, bn2w, bn2b, out);
}